// round 3
// baseline (speedup 1.0000x reference)
#include <cuda_runtime.h>
#include <math.h>

// SafetyConstraint CBF: out = clip(clip(grad(h).sdot,-100,100) + 2h, -20, 20)
// R3: persistent grid-stride blocks with double-buffered cp.async pipeline —
// prefetch tile t+1 while computing tile t, keeping DRAM loads in flight
// continuously instead of bulk-synchronous load->compute phases.

#define TPB 256
#define TILE 256                 // rows per tile
#define TILE_F (TILE * 18)       // 4608 floats = 18432 B per stage

__device__ __forceinline__ float cbf_row(const float* __restrict__ r, float act0)
{
    const float px = r[0],  py = r[1],  pz = r[2];
    const float qw = r[3],  qx = r[4],  qy = r[5],  qz = r[6];
    const float vx = r[7],  vy = r[8],  vz = r[9];
    const float wx = r[10], wy = r[11], wz = r[12];

    const float thrust = fminf(fmaxf(act0, 0.0f), 0.35f);

    const float nsq = qw*qw + qx*qx + qy*qy + qz*qz;
    const float nrm = sqrtf(nsq);
    const float inv = 1.0f / (nrm + 1e-8f);
    const float uw = qw * inv, ux = qx * inv, uy = qy * inv, uz = qz * inv;

    const float b0 = pz - 0.4f;
    const float b1 = 1.6f - pz;
    const float b2 = 1.0f - px * px;
    const float b3 = 1.0f - py * py;
    const float b4 = 0.16f - (vx*vx + vy*vy + vz*vz);
    const float aq = fabsf(uw);
    const float qc = fminf(fmaxf(aq, 0.1f), 1.0f);
    const float b5 = qc - 0.75f;

    const float BETA = 5.0f;
    const float bmin = fminf(fminf(fminf(b0, b1), fminf(b2, b3)), fminf(b4, b5));
    const float e0 = __expf(-BETA * (b0 - bmin));
    const float e1 = __expf(-BETA * (b1 - bmin));
    const float e2 = __expf(-BETA * (b2 - bmin));
    const float e3 = __expf(-BETA * (b3 - bmin));
    const float e4 = __expf(-BETA * (b4 - bmin));
    const float e5 = __expf(-BETA * (b5 - bmin));
    const float S = e0 + e1 + e2 + e3 + e4 + e5;
    const float invS = 1.0f / S;
    const float h = bmin - __logf(S) * (1.0f / BETA);

    const float p0 = e0 * invS, p1 = e1 * invS, p2 = e2 * invS;
    const float p3 = e3 * invS, p4 = e4 * invS, p5 = e5 * invS;

    const float gpx = -2.0f * px * p2;
    const float gpy = -2.0f * py * p3;
    const float gpz = p0 - p1;
    const float gvz = -2.0f * p4 * vz;

    const float active = (aq > 0.1f && aq < 1.0f) ? 1.0f : 0.0f;
    const float sgn = (uw >= 0.0f) ? 1.0f : -1.0f;
    const float coef = p5 * sgn * active;
    const float common = coef * uw * inv / nrm;
    const float gq0 = coef * inv - common * qw;
    const float gq1 = -common * qx;
    const float gq2 = -common * qy;
    const float gq3 = -common * qz;

    const float qd0 = 0.5f * (-ux * wx - uy * wy - uz * wz);
    const float qd1 = 0.5f * ( uw * wx + uy * wz - uz * wy);
    const float qd2 = 0.5f * ( uw * wy + uz * wx - ux * wz);
    const float qd3 = 0.5f * ( uw * wz + ux * wy - uy * wx);
    float R33 = 1.0f - 2.0f * (ux * ux + uy * uy);
    R33 = fminf(fmaxf(R33, -1.0f), 1.0f);
    const float az = thrust * R33 * (1.0f / 0.027f) - 9.81f;

    float lie = gpx * vx + gpy * vy + gpz * vz;
    lie += gq0 * qd0 + gq1 * qd1 + gq2 * qd2 + gq3 * qd3;
    lie += gvz * az;

    const float h_dot = fminf(fmaxf(lie, -100.0f), 100.0f);
    return fminf(fmaxf(h_dot + 2.0f * h, -20.0f), 20.0f);
}

// Issue async staging of one tile into smem stage `buf`. One commit_group per call.
__device__ __forceinline__ void prefetch_tile(
    float (*s)[TILE_F], int buf,
    const float* __restrict__ state, long tileBase, int rows)
{
    unsigned dst_base = (unsigned)__cvta_generic_to_shared(&s[buf][0]);
    if (rows == TILE) {
        const float4* g4 = reinterpret_cast<const float4*>(state + tileBase * 18);
        // 1152 float4 = 4.5 per thread (predicated last trip)
        #pragma unroll
        for (int k = 0; k < 5; k++) {
            int i = threadIdx.x + k * TPB;
            if (i < TILE_F / 4) {
                unsigned dst = dst_base + i * 16u;
                asm volatile("cp.async.cg.shared.global [%0], [%1], 16;\n"
                             :: "r"(dst), "l"(g4 + i));
            }
        }
    } else {
        // partial tile: scalar 4B cp.async
        const float* g = state + tileBase * 18;
        for (int i = threadIdx.x; i < rows * 18; i += TPB) {
            unsigned dst = dst_base + i * 4u;
            asm volatile("cp.async.ca.shared.global [%0], [%1], 4;\n"
                         :: "r"(dst), "l"(g + i));
        }
    }
    asm volatile("cp.async.commit_group;\n" ::: "memory");
}

__global__ __launch_bounds__(TPB) void cbf_kernel(
    const float* __restrict__ state,   // [n, 18]
    const float* __restrict__ action,  // [n, 4]
    float* __restrict__ out,           // [n]
    int n)
{
    __shared__ float s[2][TILE_F];     // 36864 B

    const int T = (n + TILE - 1) / TILE;   // number of tiles
    int tile = blockIdx.x;
    if (tile >= T) return;

    // Prologue: prefetch first tile
    {
        long base = (long)tile * TILE;
        int rows = min(TILE, n - (int)base);
        prefetch_tile(s, 0, state, base, rows);
    }

    int buf = 0;
    for (; tile < T; tile += gridDim.x) {
        const long base = (long)tile * TILE;
        const int rows = min(TILE, n - (int)base);
        const int next = tile + gridDim.x;
        const bool hasNext = (next < T);

        // Prefetch next tile into the other buffer (last read 2 iters ago,
        // protected by the trailing __syncthreads of the previous iteration).
        if (hasNext) {
            long nbase = (long)next * TILE;
            int nrows = min(TILE, n - (int)nbase);
            prefetch_tile(s, buf ^ 1, state, nbase, nrows);
        }

        // Action word for this tile: issue LDG before the wait so its
        // latency hides under the cp.async drain.
        const int row = (int)base + threadIdx.x;
        float a0 = 0.0f;
        if (threadIdx.x < rows) {
            a0 = __ldg(action + (size_t)row * 4);
        }

        // Wait for current tile (allow the just-issued next group to remain
        // in flight).
        if (hasNext) {
            asm volatile("cp.async.wait_group 1;\n" ::: "memory");
        } else {
            asm volatile("cp.async.wait_group 0;\n" ::: "memory");
        }
        __syncthreads();

        if (threadIdx.x < rows) {
            out[row] = cbf_row(&s[buf][threadIdx.x * 18], a0);
        }
        __syncthreads();   // all reads of s[buf] done before it is re-filled

        buf ^= 1;
    }
}

extern "C" void kernel_launch(void* const* d_in, const int* in_sizes, int n_in,
                              void* d_out, int out_size)
{
    const float* state  = (const float*)d_in[0];
    const float* action = (const float*)d_in[1];
    float* out = (float*)d_out;

    const int n = out_size;
    const int T = (n + TILE - 1) / TILE;
    int grid = 148 * 6;                 // ~6 blocks/SM resident target
    if (grid > T) grid = T;
    cbf_kernel<<<grid, TPB>>>(state, action, out, n);
}

// round 4
// speedup vs baseline: 1.2221x; 1.2221x over previous
#include <cuda_runtime.h>
#include <math.h>

// SafetyConstraint CBF: out = clip(clip(grad(h).sdot,-100,100) + 2h, -20, 20)
// R4: R2's bulk-synchronous block structure (which measured best), upgraded to
// two cp.async stages per block so compute of stage A overlaps the in-flight
// loads of stage B. Exact 9x16B cp.async per thread per stage (no predication).

#define TPB 128
#define SROWS 256                 // rows per stage
#define SF (SROWS * 18)           // 4608 floats = 18432 B per stage
#define RPB (SROWS * 2)           // 512 rows per block

__device__ __forceinline__ float cbf_row(const float* __restrict__ r, float act0)
{
    const float px = r[0],  py = r[1],  pz = r[2];
    const float qw = r[3],  qx = r[4],  qy = r[5],  qz = r[6];
    const float vx = r[7],  vy = r[8],  vz = r[9];
    const float wx = r[10], wy = r[11], wz = r[12];

    const float thrust = fminf(fmaxf(act0, 0.0f), 0.35f);

    const float nsq = qw*qw + qx*qx + qy*qy + qz*qz;
    const float nrm = sqrtf(nsq);
    const float inv = 1.0f / (nrm + 1e-8f);
    const float uw = qw * inv, ux = qx * inv, uy = qy * inv, uz = qz * inv;

    const float b0 = pz - 0.4f;
    const float b1 = 1.6f - pz;
    const float b2 = 1.0f - px * px;
    const float b3 = 1.0f - py * py;
    const float b4 = 0.16f - (vx*vx + vy*vy + vz*vz);
    const float aq = fabsf(uw);
    const float qc = fminf(fmaxf(aq, 0.1f), 1.0f);
    const float b5 = qc - 0.75f;

    const float BETA = 5.0f;
    const float bmin = fminf(fminf(fminf(b0, b1), fminf(b2, b3)), fminf(b4, b5));
    const float e0 = __expf(-BETA * (b0 - bmin));
    const float e1 = __expf(-BETA * (b1 - bmin));
    const float e2 = __expf(-BETA * (b2 - bmin));
    const float e3 = __expf(-BETA * (b3 - bmin));
    const float e4 = __expf(-BETA * (b4 - bmin));
    const float e5 = __expf(-BETA * (b5 - bmin));
    const float S = e0 + e1 + e2 + e3 + e4 + e5;
    const float invS = 1.0f / S;
    const float h = bmin - __logf(S) * (1.0f / BETA);

    const float p0 = e0 * invS, p1 = e1 * invS, p2 = e2 * invS;
    const float p3 = e3 * invS, p4 = e4 * invS, p5 = e5 * invS;

    const float gpx = -2.0f * px * p2;
    const float gpy = -2.0f * py * p3;
    const float gpz = p0 - p1;
    const float gvz = -2.0f * p4 * vz;

    const float active = (aq > 0.1f && aq < 1.0f) ? 1.0f : 0.0f;
    const float sgn = (uw >= 0.0f) ? 1.0f : -1.0f;
    const float coef = p5 * sgn * active;
    const float common = coef * uw * inv / nrm;
    const float gq0 = coef * inv - common * qw;
    const float gq1 = -common * qx;
    const float gq2 = -common * qy;
    const float gq3 = -common * qz;

    const float qd0 = 0.5f * (-ux * wx - uy * wy - uz * wz);
    const float qd1 = 0.5f * ( uw * wx + uy * wz - uz * wy);
    const float qd2 = 0.5f * ( uw * wy + uz * wx - ux * wz);
    const float qd3 = 0.5f * ( uw * wz + ux * wy - uy * wx);
    float R33 = 1.0f - 2.0f * (ux * ux + uy * uy);
    R33 = fminf(fmaxf(R33, -1.0f), 1.0f);
    const float az = thrust * R33 * (1.0f / 0.027f) - 9.81f;

    float lie = gpx * vx + gpy * vy + gpz * vz;
    lie += gq0 * qd0 + gq1 * qd1 + gq2 * qd2 + gq3 * qd3;
    lie += gvz * az;

    const float h_dot = fminf(fmaxf(lie, -100.0f), 100.0f);
    return fminf(fmaxf(h_dot + 2.0f * h, -20.0f), 20.0f);
}

// Stage one 256-row chunk: 9 x 16B cp.async per thread, exact, one group.
__device__ __forceinline__ void issue_stage(float* sdst, const float* __restrict__ gsrc)
{
    unsigned dst_base = (unsigned)__cvta_generic_to_shared(sdst);
    const float4* g4 = reinterpret_cast<const float4*>(gsrc);
    #pragma unroll
    for (int k = 0; k < 9; k++) {
        int i = threadIdx.x + k * TPB;
        unsigned dst = dst_base + i * 16u;
        asm volatile("cp.async.cg.shared.global [%0], [%1], 16;\n"
                     :: "r"(dst), "l"(g4 + i));
    }
    asm volatile("cp.async.commit_group;\n" ::: "memory");
}

__global__ __launch_bounds__(TPB) void cbf_kernel(
    const float* __restrict__ state,   // [n, 18]
    const float* __restrict__ action,  // [n, 4]
    float* __restrict__ out,           // [n]
    int n)
{
    __shared__ float s[2][SF];         // 36864 B

    const int base = blockIdx.x * RPB;
    const int tid = threadIdx.x;

    if (base + RPB <= n) {
        // Issue both stages immediately: 36 KB in flight per block.
        issue_stage(s[0], state + (size_t)base * 18);
        issue_stage(s[1], state + (size_t)(base + SROWS) * 18);

        // Action (thrust) loads for all 4 rows this thread owns — in flight
        // under the cp.async drain.
        const int r0 = base + tid;
        const int r1 = r0 + TPB;
        const int r2 = base + SROWS + tid;
        const int r3 = r2 + TPB;
        const float a0 = __ldg(action + (size_t)r0 * 4);
        const float a1 = __ldg(action + (size_t)r1 * 4);
        const float a2 = __ldg(action + (size_t)r2 * 4);
        const float a3 = __ldg(action + (size_t)r3 * 4);

        // Stage A ready; stage B (18 KB) still in flight during compute.
        asm volatile("cp.async.wait_group 1;\n" ::: "memory");
        __syncthreads();

        out[r0] = cbf_row(&s[0][tid * 18], a0);
        out[r1] = cbf_row(&s[0][(tid + TPB) * 18], a1);

        asm volatile("cp.async.wait_group 0;\n" ::: "memory");
        __syncthreads();

        out[r2] = cbf_row(&s[1][tid * 18], a2);
        out[r3] = cbf_row(&s[1][(tid + TPB) * 18], a3);
    } else {
        // Tail block: guarded scalar staging + compute.
        int cnt = n - base;
        if (cnt < 0) cnt = 0;
        float* sf = &s[0][0];
        for (int i = tid; i < cnt * 18; i += TPB) {
            // stays within s[0..1] (cnt*18 <= RPB*18 = 2*SF)
            sf[i] = state[(size_t)base * 18 + i];
        }
        __syncthreads();
        for (int l = tid; l < cnt; l += TPB) {
            const int row = base + l;
            const float a0 = action[(size_t)row * 4];
            out[row] = cbf_row(sf + l * 18, a0);
        }
    }
}

extern "C" void kernel_launch(void* const* d_in, const int* in_sizes, int n_in,
                              void* d_out, int out_size)
{
    const float* state  = (const float*)d_in[0];
    const float* action = (const float*)d_in[1];
    float* out = (float*)d_out;

    const int n = out_size;
    const int grid = (n + RPB - 1) / RPB;
    cbf_kernel<<<grid, TPB>>>(state, action, out, n);
}

// round 5
// speedup vs baseline: 1.2505x; 1.0232x over previous
#include <cuda_runtime.h>
#include <math.h>

// SafetyConstraint CBF: out = clip(clip(grad(h).sdot,-100,100) + 2h, -20, 20)
// R5: two-stage cp.async block (best structure so far) at half grain:
// 128-row stages, 256 rows/block, grid=8192. Raises occupancy 35%->62.5%,
// halves block duration (smaller drain tail), keeps 18KB/block in flight.

#define TPB 128
#define SROWS 128                 // rows per stage
#define SF (SROWS * 18)           // 2304 floats = 9216 B per stage
#define RPB (SROWS * 2)           // 256 rows per block

__device__ __forceinline__ float cbf_row(const float* __restrict__ r, float act0)
{
    const float px = r[0],  py = r[1],  pz = r[2];
    const float qw = r[3],  qx = r[4],  qy = r[5],  qz = r[6];
    const float vx = r[7],  vy = r[8],  vz = r[9];
    const float wx = r[10], wy = r[11], wz = r[12];

    const float thrust = fminf(fmaxf(act0, 0.0f), 0.35f);

    const float nsq = qw*qw + qx*qx + qy*qy + qz*qz;
    const float nrm = sqrtf(nsq);
    const float inv = 1.0f / (nrm + 1e-8f);
    const float uw = qw * inv, ux = qx * inv, uy = qy * inv, uz = qz * inv;

    const float b0 = pz - 0.4f;
    const float b1 = 1.6f - pz;
    const float b2 = 1.0f - px * px;
    const float b3 = 1.0f - py * py;
    const float b4 = 0.16f - (vx*vx + vy*vy + vz*vz);
    const float aq = fabsf(uw);
    const float qc = fminf(fmaxf(aq, 0.1f), 1.0f);
    const float b5 = qc - 0.75f;

    const float BETA = 5.0f;
    const float bmin = fminf(fminf(fminf(b0, b1), fminf(b2, b3)), fminf(b4, b5));
    const float e0 = __expf(-BETA * (b0 - bmin));
    const float e1 = __expf(-BETA * (b1 - bmin));
    const float e2 = __expf(-BETA * (b2 - bmin));
    const float e3 = __expf(-BETA * (b3 - bmin));
    const float e4 = __expf(-BETA * (b4 - bmin));
    const float e5 = __expf(-BETA * (b5 - bmin));
    const float S = e0 + e1 + e2 + e3 + e4 + e5;
    const float invS = 1.0f / S;
    const float h = bmin - __logf(S) * (1.0f / BETA);

    const float p0 = e0 * invS, p1 = e1 * invS, p2 = e2 * invS;
    const float p3 = e3 * invS, p4 = e4 * invS, p5 = e5 * invS;

    const float gpx = -2.0f * px * p2;
    const float gpy = -2.0f * py * p3;
    const float gpz = p0 - p1;
    const float gvz = -2.0f * p4 * vz;

    const float active = (aq > 0.1f && aq < 1.0f) ? 1.0f : 0.0f;
    const float sgn = (uw >= 0.0f) ? 1.0f : -1.0f;
    const float coef = p5 * sgn * active;
    const float common = coef * uw * inv / nrm;
    const float gq0 = coef * inv - common * qw;
    const float gq1 = -common * qx;
    const float gq2 = -common * qy;
    const float gq3 = -common * qz;

    const float qd0 = 0.5f * (-ux * wx - uy * wy - uz * wz);
    const float qd1 = 0.5f * ( uw * wx + uy * wz - uz * wy);
    const float qd2 = 0.5f * ( uw * wy + uz * wx - ux * wz);
    const float qd3 = 0.5f * ( uw * wz + ux * wy - uy * wx);
    float R33 = 1.0f - 2.0f * (ux * ux + uy * uy);
    R33 = fminf(fmaxf(R33, -1.0f), 1.0f);
    const float az = thrust * R33 * (1.0f / 0.027f) - 9.81f;

    float lie = gpx * vx + gpy * vy + gpz * vz;
    lie += gq0 * qd0 + gq1 * qd1 + gq2 * qd2 + gq3 * qd3;
    lie += gvz * az;

    const float h_dot = fminf(fmaxf(lie, -100.0f), 100.0f);
    return fminf(fmaxf(h_dot + 2.0f * h, -20.0f), 20.0f);
}

// Stage one 128-row chunk: 576 float4 = 4.5/thread (5th trip predicated).
__device__ __forceinline__ void issue_stage(float* sdst, const float* __restrict__ gsrc)
{
    unsigned dst_base = (unsigned)__cvta_generic_to_shared(sdst);
    const float4* g4 = reinterpret_cast<const float4*>(gsrc);
    #pragma unroll
    for (int k = 0; k < 5; k++) {
        int i = threadIdx.x + k * TPB;
        if (i < SF / 4) {
            unsigned dst = dst_base + i * 16u;
            asm volatile("cp.async.cg.shared.global [%0], [%1], 16;\n"
                         :: "r"(dst), "l"(g4 + i));
        }
    }
    asm volatile("cp.async.commit_group;\n" ::: "memory");
}

__global__ __launch_bounds__(TPB) void cbf_kernel(
    const float* __restrict__ state,   // [n, 18]
    const float* __restrict__ action,  // [n, 4]
    float* __restrict__ out,           // [n]
    int n)
{
    __shared__ float s[2][SF];         // 18432 B

    const int base = blockIdx.x * RPB;
    const int tid = threadIdx.x;

    if (base + RPB <= n) {
        // Both stages in flight immediately: 18.4 KB per block.
        issue_stage(s[0], state + (size_t)base * 18);
        issue_stage(s[1], state + (size_t)(base + SROWS) * 18);

        // Thrust loads for both rows — latency hides under cp.async drain.
        const int r0 = base + tid;
        const int r1 = base + SROWS + tid;
        const float a0 = __ldg(action + (size_t)r0 * 4);
        const float a1 = __ldg(action + (size_t)r1 * 4);

        // Stage A ready; stage B still in flight during compute of A.
        asm volatile("cp.async.wait_group 1;\n" ::: "memory");
        __syncthreads();

        out[r0] = cbf_row(&s[0][tid * 18], a0);

        asm volatile("cp.async.wait_group 0;\n" ::: "memory");
        __syncthreads();

        out[r1] = cbf_row(&s[1][tid * 18], a1);
    } else {
        // Tail block: guarded scalar staging + compute.
        int cnt = n - base;
        if (cnt < 0) cnt = 0;
        float* sf = &s[0][0];
        for (int i = tid; i < cnt * 18; i += TPB) {
            sf[i] = state[(size_t)base * 18 + i];   // cnt*18 <= 2*SF
        }
        __syncthreads();
        for (int l = tid; l < cnt; l += TPB) {
            const int row = base + l;
            const float a0 = action[(size_t)row * 4];
            out[row] = cbf_row(sf + l * 18, a0);
        }
    }
}

extern "C" void kernel_launch(void* const* d_in, const int* in_sizes, int n_in,
                              void* d_out, int out_size)
{
    const float* state  = (const float*)d_in[0];
    const float* action = (const float*)d_in[1];
    float* out = (float*)d_out;

    const int n = out_size;
    const int grid = (n + RPB - 1) / RPB;
    cbf_kernel<<<grid, TPB>>>(state, action, out, n);
}

// round 6
// speedup vs baseline: 1.2875x; 1.0296x over previous
#include <cuda_runtime.h>
#include <math.h>

// SafetyConstraint CBF: out = clip(clip(grad(h).sdot,-100,100) + 2h, -20, 20)
// R6: warp-autonomous two-stage cp.async pipeline. Each warp stages and
// consumes its own 32-row chunks (cp.async.wait_group + __syncwarp only —
// no block barriers), so the 4 warps stream independently and the SM's
// DRAM request stream stays smooth. launch_bounds(128,12) for 75% occ.

#define TPB 128
#define WROWS 32                  // rows per warp per stage
#define WSF (WROWS * 18)          // 576 floats = 2304 B per warp-stage

__device__ __forceinline__ float cbf_row(const float* __restrict__ r, float act0)
{
    const float px = r[0],  py = r[1],  pz = r[2];
    const float qw = r[3],  qx = r[4],  qy = r[5],  qz = r[6];
    const float vx = r[7],  vy = r[8],  vz = r[9];
    const float wx = r[10], wy = r[11], wz = r[12];

    const float thrust = fminf(fmaxf(act0, 0.0f), 0.35f);

    // quaternion normalization via rsqrt (+1st-order eps correction;
    // error ~1e-16 vs reference's 1/(nrm+1e-8))
    const float nsq = qw*qw + qx*qx + qy*qy + qz*qz;
    const float rs = rsqrtf(nsq);                 // = 1/nrm
    const float inv = rs - 1e-8f * rs * rs;       // ~ 1/(nrm+eps)
    const float uw = qw * inv, ux = qx * inv, uy = qy * inv, uz = qz * inv;

    const float b0 = pz - 0.4f;
    const float b1 = 1.6f - pz;
    const float b2 = 1.0f - px * px;
    const float b3 = 1.0f - py * py;
    const float b4 = 0.16f - (vx*vx + vy*vy + vz*vz);
    const float aq = fabsf(uw);
    const float qc = fminf(fmaxf(aq, 0.1f), 1.0f);
    const float b5 = qc - 0.75f;

    const float BETA = 5.0f;
    const float bmin = fminf(fminf(fminf(b0, b1), fminf(b2, b3)), fminf(b4, b5));
    const float e0 = __expf(-BETA * (b0 - bmin));
    const float e1 = __expf(-BETA * (b1 - bmin));
    const float e2 = __expf(-BETA * (b2 - bmin));
    const float e3 = __expf(-BETA * (b3 - bmin));
    const float e4 = __expf(-BETA * (b4 - bmin));
    const float e5 = __expf(-BETA * (b5 - bmin));
    const float S = e0 + e1 + e2 + e3 + e4 + e5;
    const float invS = 1.0f / S;
    const float h = bmin - __logf(S) * (1.0f / BETA);

    const float p0 = e0 * invS, p1 = e1 * invS, p2 = e2 * invS;
    const float p3 = e3 * invS, p4 = e4 * invS, p5 = e5 * invS;

    const float gpx = -2.0f * px * p2;
    const float gpy = -2.0f * py * p3;
    const float gpz = p0 - p1;
    const float gvz = -2.0f * p4 * vz;

    const float active = (aq > 0.1f && aq < 1.0f) ? 1.0f : 0.0f;
    const float sgn = (uw >= 0.0f) ? 1.0f : -1.0f;
    const float coef = p5 * sgn * active;
    const float common = coef * uw * inv * rs;    // inv/nrm == inv*rs
    const float gq0 = coef * inv - common * qw;
    const float gq1 = -common * qx;
    const float gq2 = -common * qy;
    const float gq3 = -common * qz;

    const float qd0 = 0.5f * (-ux * wx - uy * wy - uz * wz);
    const float qd1 = 0.5f * ( uw * wx + uy * wz - uz * wy);
    const float qd2 = 0.5f * ( uw * wy + uz * wx - ux * wz);
    const float qd3 = 0.5f * ( uw * wz + ux * wy - uy * wx);
    float R33 = 1.0f - 2.0f * (ux * ux + uy * uy);
    R33 = fminf(fmaxf(R33, -1.0f), 1.0f);
    const float az = thrust * R33 * (1.0f / 0.027f) - 9.81f;

    float lie = gpx * vx + gpy * vy + gpz * vz;
    lie += gq0 * qd0 + gq1 * qd1 + gq2 * qd2 + gq3 * qd3;
    lie += gvz * az;

    const float h_dot = fminf(fmaxf(lie, -100.0f), 100.0f);
    return fminf(fmaxf(h_dot + 2.0f * h, -20.0f), 20.0f);
}

// Warp-local stage: 32 rows = 144 float4 -> 4 full + 1 half-warp-predicated
// cp.async per lane. One commit_group.
__device__ __forceinline__ void issue_warp_stage(
    float* sdst, const float* __restrict__ gsrc, int lane)
{
    unsigned dst_base = (unsigned)__cvta_generic_to_shared(sdst);
    const float4* g4 = reinterpret_cast<const float4*>(gsrc);
    #pragma unroll
    for (int k = 0; k < 4; k++) {
        int i = lane + k * 32;
        asm volatile("cp.async.cg.shared.global [%0], [%1], 16;\n"
                     :: "r"(dst_base + i * 16u), "l"(g4 + i));
    }
    if (lane < 16) {
        int i = lane + 128;
        asm volatile("cp.async.cg.shared.global [%0], [%1], 16;\n"
                     :: "r"(dst_base + i * 16u), "l"(g4 + i));
    }
    asm volatile("cp.async.commit_group;\n" ::: "memory");
}

__global__ __launch_bounds__(TPB, 12) void cbf_kernel(
    const float* __restrict__ state,   // [n, 18]
    const float* __restrict__ action,  // [n, 4]
    float* __restrict__ out,           // [n]
    int n)
{
    __shared__ float s[4][2][WSF];     // 18432 B

    const int warp = threadIdx.x >> 5;
    const int lane = threadIdx.x & 31;
    const int base = blockIdx.x * (TPB * 2) + warp * (WROWS * 2);

    if (base + WROWS * 2 <= n && (blockIdx.x + 1) * (TPB * 2) <= n) {
        // Two warp-private stages in flight immediately.
        issue_warp_stage(s[warp][0], state + (size_t)base * 18, lane);
        issue_warp_stage(s[warp][1], state + (size_t)(base + WROWS) * 18, lane);

        const int r0 = base + lane;
        const int r1 = base + WROWS + lane;
        const float a0 = __ldg(action + (size_t)r0 * 4);
        const float a1 = __ldg(action + (size_t)r1 * 4);

        // Stage A done (stage B still in flight during compute of A).
        asm volatile("cp.async.wait_group 1;\n" ::: "memory");
        __syncwarp();
        out[r0] = cbf_row(&s[warp][0][lane * 18], a0);

        asm volatile("cp.async.wait_group 0;\n" ::: "memory");
        __syncwarp();
        out[r1] = cbf_row(&s[warp][1][lane * 18], a1);
    } else {
        // Tail: guarded scalar staging + compute (block-wide, rare).
        const int bbase = blockIdx.x * (TPB * 2);
        int cnt = n - bbase;
        if (cnt < 0) cnt = 0;
        if (cnt > TPB * 2) cnt = TPB * 2;
        float* sf = &s[0][0][0];
        for (int i = threadIdx.x; i < cnt * 18; i += TPB) {
            sf[i] = state[(size_t)bbase * 18 + i];
        }
        __syncthreads();
        for (int l = threadIdx.x; l < cnt; l += TPB) {
            const int row = bbase + l;
            const float a0 = action[(size_t)row * 4];
            out[row] = cbf_row(sf + l * 18, a0);
        }
    }
}

extern "C" void kernel_launch(void* const* d_in, const int* in_sizes, int n_in,
                              void* d_out, int out_size)
{
    const float* state  = (const float*)d_in[0];
    const float* action = (const float*)d_in[1];
    float* out = (float*)d_out;

    const int n = out_size;
    const int grid = (n + TPB * 2 - 1) / (TPB * 2);
    cbf_kernel<<<grid, TPB>>>(state, action, out, n);
}